// round 8
// baseline (speedup 1.0000x reference)
#include <cuda_runtime.h>
#include <cstdint>

// RGCNHighMem: out[dst] += feat[src] @ W[etype]
// v8: v7 + dup-pack staging (Phase A stores feat quads as dup-pair float4s so
// Phase B reads FFMA2-ready f32x2 operands, no extraction movs) + dst indices
// stashed in registers across phases.
//   tile = 32 edges/warp; lane (m, p) owns edges {m, m+16}, cols 16p..16p+15.

#define RELS   64
#define EPB    256          // edges per main-kernel block (4 warps x 2 x 32)
#define SCHUNK 512          // edges per scatter block
#define CAP    8192         // per-relation bucket capacity (max expected ~3.4K)
#define MAXK   (CAP / EPB)  // 32 chunks per relation

__device__ int g_cnt[RELS];
__device__ unsigned long long g_edges[RELS * CAP];  // packed (src | dst<<32)

// Single-pass scatter + d_out zeroing.
__global__ __launch_bounds__(256)
void k_scatter(const int* __restrict__ src, const int* __restrict__ dst,
               const int* __restrict__ et, int E,
               float4* __restrict__ out4, int nout4) {
    __shared__ int cnt[RELS], base[RELS];
    int tid = threadIdx.x;

    for (int i = blockIdx.x * 256 + tid; i < nout4; i += gridDim.x * 256)
        out4[i] = make_float4(0.f, 0.f, 0.f, 0.f);

    int b0 = blockIdx.x * SCHUNK;
    int b1 = min(E, b0 + SCHUNK);
    if (tid < RELS) cnt[tid] = 0;
    __syncthreads();

    int t0 = -1, t1 = -1;
    int e0 = b0 + tid, e1 = b0 + tid + 256;
    if (e0 < b1) { t0 = et[e0]; atomicAdd(&cnt[t0], 1); }
    if (e1 < b1) { t1 = et[e1]; atomicAdd(&cnt[t1], 1); }
    __syncthreads();

    if (tid < RELS) {
        int v = cnt[tid];
        base[tid] = v ? atomicAdd(&g_cnt[tid], v) : 0;
        cnt[tid] = 0;
    }
    __syncthreads();

    if (t0 >= 0) {
        int p = base[t0] + atomicAdd(&cnt[t0], 1);
        g_edges[t0 * CAP + p] =
            (unsigned long long)(unsigned)src[e0] |
            ((unsigned long long)(unsigned)dst[e0] << 32);
    }
    if (t1 >= 0) {
        int p = base[t1] + atomicAdd(&cnt[t1], 1);
        g_edges[t1 * CAP + p] =
            (unsigned long long)(unsigned)src[e1] |
            ((unsigned long long)(unsigned)dst[e1] << 32);
    }
}

__global__ __launch_bounds__(128, 6)
void k_main(const float4* __restrict__ feat4, const float4* __restrict__ W4,
            float* __restrict__ out) {
    int r = blockIdx.x >> 5;            // MAXK = 32
    int kk = blockIdx.x & (MAXK - 1);
    int cnt = g_cnt[r];
    int segs = kk * EPB;
    if (segs >= cnt) return;            // block-uniform
    int sege = min(cnt, segs + EPB);
    const unsigned long long* eb = g_edges + (size_t)r * CAP;

    __shared__ float4 Wsh[256];              // W[r]: [32 rows][8 quads]
    // per-warp stage: 32 rows x (16 dup-pair float4 + 1 pad) = 17 f4 stride
    __shared__ float4 stage[4][32 * 17];

    int tid = threadIdx.x;
    Wsh[tid]       = W4[r * 256 + tid];
    Wsh[tid + 128] = W4[r * 256 + tid + 128];
    __syncthreads();
    const ulonglong2* Ws2 = (const ulonglong2*)Wsh;

    int w = tid >> 5, l = tid & 31;
    int m = l & 15, p = l >> 4;          // edges {m, m+16}, cols 16p..16p+15
    int eh4 = l >> 3, c = l & 7;         // cooperative phases
    float4* st = stage[w];
    const ulonglong2* WsP = Ws2 + p * 4;

    #pragma unroll 1
    for (int t = 0; t < 2; t++) {
        int e0 = segs + w * 64 + t * 32;
        if (e0 >= sege) break;

        // ---- Phase A: cooperative gather; stage dup-pairs; stash dst ----
        int dreg[8];
        #pragma unroll
        for (int g = 0; g < 8; g++) {
            int row = g * 4 + eh4;
            int e = min(e0 + row, sege - 1);
            unsigned long long pk = eb[e];          // 8-lane dup -> 1 line
            int s = (int)(unsigned)pk;
            dreg[g] = (int)(pk >> 32);
            float4 f = feat4[s * 8 + c];            // 4 rows per LDG.128
            st[row * 17 + c * 2]     = make_float4(f.x, f.x, f.y, f.y);
            st[row * 17 + c * 2 + 1] = make_float4(f.z, f.z, f.w, f.w);
        }
        __syncwarp();

        // ---- Phase B: edges m, m+16; 16 f32x2 acc chains; dup operands ----
        unsigned long long aA[8], aB[8];
        #pragma unroll
        for (int j = 0; j < 8; j++) { aA[j] = 0ULL; aB[j] = 0ULL; }

        const ulonglong2* rowA = (const ulonglong2*)(st + m * 17);
        const ulonglong2* rowB = (const ulonglong2*)(st + (m + 16) * 17);

        #pragma unroll
        for (int q = 0; q < 8; q++) {
            // dup-pairs: (x,x),(y,y) then (z,z),(w,w) of feat quad q
            ulonglong2 dA0 = rowA[2 * q];
            ulonglong2 dA1 = rowA[2 * q + 1];
            ulonglong2 dB0 = rowB[2 * q];
            ulonglong2 dB1 = rowB[2 * q + 1];
            #pragma unroll
            for (int tt = 0; tt < 4; tt++) {
                int i = 4 * q + tt;
                unsigned long long dA = (tt == 0) ? dA0.x : (tt == 1) ? dA0.y
                                       : (tt == 2) ? dA1.x : dA1.y;
                unsigned long long dB = (tt == 0) ? dB0.x : (tt == 1) ? dB0.y
                                       : (tt == 2) ? dB1.x : dB1.y;
                #pragma unroll
                for (int hh = 0; hh < 4; hh++) {
                    ulonglong2 wv = WsP[i * 8 + hh];  // 2-addr broadcast LDS
                    asm("fma.rn.f32x2 %0, %1, %2, %0;"
                        : "+l"(aA[2 * hh]) : "l"(dA), "l"(wv.x));
                    asm("fma.rn.f32x2 %0, %1, %2, %0;"
                        : "+l"(aA[2 * hh + 1]) : "l"(dA), "l"(wv.y));
                    asm("fma.rn.f32x2 %0, %1, %2, %0;"
                        : "+l"(aB[2 * hh]) : "l"(dB), "l"(wv.x));
                    asm("fma.rn.f32x2 %0, %1, %2, %0;"
                        : "+l"(aB[2 * hh + 1]) : "l"(dB), "l"(wv.y));
                }
            }
        }

        // Store acc quads (cols 16p+4hh..+3) back to stage rows m, m+16.
        #pragma unroll
        for (int hh = 0; hh < 4; hh++) {
            unsigned x, y, z, u;
            asm("mov.b64 {%0,%1}, %2;" : "=r"(x), "=r"(y) : "l"(aA[2 * hh]));
            asm("mov.b64 {%0,%1}, %2;" : "=r"(z), "=r"(u) : "l"(aA[2 * hh + 1]));
            st[m * 17 + p * 4 + hh] =
                make_float4(__uint_as_float(x), __uint_as_float(y),
                            __uint_as_float(z), __uint_as_float(u));
            asm("mov.b64 {%0,%1}, %2;" : "=r"(x), "=r"(y) : "l"(aB[2 * hh]));
            asm("mov.b64 {%0,%1}, %2;" : "=r"(z), "=r"(u) : "l"(aB[2 * hh + 1]));
            st[(m + 16) * 17 + p * 4 + hh] =
                make_float4(__uint_as_float(x), __uint_as_float(y),
                            __uint_as_float(z), __uint_as_float(u));
        }
        __syncwarp();

        // ---- Phase C: cooperative scatter, 4 dst rows per red.v4 ----
        #pragma unroll
        for (int g = 0; g < 8; g++) {
            int row = g * 4 + eh4;
            if (e0 + row < sege) {
                float4 a = st[row * 17 + c];
                float* pp = out + (size_t)dreg[g] * 32 + c * 4;
                asm volatile("red.global.add.v4.f32 [%0], {%1,%2,%3,%4};"
                             :: "l"(pp), "f"(a.x), "f"(a.y), "f"(a.z), "f"(a.w)
                             : "memory");
            }
        }
        __syncwarp();   // stage reused by next tile's Phase A
    }
}

extern "C" void kernel_launch(void* const* d_in, const int* in_sizes, int n_in,
                              void* d_out, int out_size) {
    const float* feat = (const float*)d_in[0];
    const float* W    = (const float*)d_in[1];
    const int*   src  = (const int*)d_in[2];
    const int*   dst  = (const int*)d_in[3];
    const int*   et   = (const int*)d_in[4];
    int E = in_sizes[2];

    void* cnt_addr = nullptr;
    cudaGetSymbolAddress(&cnt_addr, g_cnt);

    cudaMemsetAsync(cnt_addr, 0, RELS * sizeof(int), 0);
    k_scatter<<<(E + SCHUNK - 1) / SCHUNK, 256>>>(src, dst, et, E,
                                                  (float4*)d_out, out_size / 4);
    k_main<<<RELS * MAXK, 128>>>((const float4*)feat, (const float4*)W,
                                 (float*)d_out);
}